// round 13
// baseline (speedup 1.0000x reference)
#include <cuda_runtime.h>
#include <cuda_fp16.h>
#include <mma.h>

using namespace nvcuda;

#define T_ 512
#define B_ 64
#define I_ 512
#define H_ 512
#define G_ 2048   // 4*H

#define LO_SCALE   2048.f
#define LO_INV     4.8828125e-4f   // 1/2048

// ---------------- scratch (device globals: allowed) ----------------
__device__ float    g_xproj[2ull * T_ * B_ * G_];   // [dir][t][b][4H]
__device__ __half   g_hh[2][2][B_][H_];             // h split hi   [buf][dir][b][h]
__device__ __half   g_hl[2][2][B_][H_];             // h split lo * 2048
__device__ __half   g_xh[(size_t)T_ * B_ * I_];     // x pre-split hi
__device__ __half   g_xl[(size_t)T_ * B_ * I_];     // x pre-split lo
__device__ __half   g_wh[2][(size_t)G_ * I_];       // W_ih pre-split hi  [dir]
__device__ __half   g_wl[2][(size_t)G_ * I_];       // W_ih pre-split lo
__device__ unsigned g_bar[2][32];                   // per-dir counters, 128B apart

__device__ __forceinline__ void split_h16(float v, __half& hi, __half& lo)
{
    hi = __float2half_rn(v);
    lo = __float2half_rn((v - __half2float(hi)) * LO_SCALE);
}

__device__ __forceinline__ unsigned h2_bits(__half a, __half b)
{
    __half2 h2 = __halves2half2(a, b);
    return *reinterpret_cast<unsigned*>(&h2);
}

__device__ __forceinline__ void stcg_u32(void* p, unsigned v)
{
    asm volatile("st.global.cg.u32 [%0], %1;" :: "l"(p), "r"(v) : "memory");
}

__device__ __forceinline__ void cp_async_cg16(void* smem, const void* gmem)
{
    unsigned sa = (unsigned)__cvta_generic_to_shared(smem);
    asm volatile("cp.async.cg.shared.global [%0], [%1], 16;" :: "r"(sa), "l"(gmem) : "memory");
}
__device__ __forceinline__ void cp_async_commit_wait()
{
    asm volatile("cp.async.commit_group;\n\tcp.async.wait_group 0;" ::: "memory");
}

__device__ __forceinline__ float fsig(float x)  { return __fdividef(1.f, 1.f + __expf(-x)); }
__device__ __forceinline__ float ftanh(float x) { return __fdividef(2.f, 1.f + __expf(-2.f * x)) - 1.f; }

// ---------------- prep: split x, W_ih into fp16 hi/lo; seed h state; reset barrier --------
__global__ void __launch_bounds__(256) prep_kernel(
    const float* __restrict__ x,
    const float* __restrict__ Wf, const float* __restrict__ Wb,
    const float* __restrict__ h0)
{
    const int gtid = blockIdx.x * blockDim.x + threadIdx.x;
    const int gsz  = gridDim.x * blockDim.x;
    if (blockIdx.x == 0 && threadIdx.x < 2) g_bar[threadIdx.x][0] = 0u;

    const int NX4 = T_ * B_ * I_ / 4;
    for (int i = gtid; i < NX4; i += gsz) {
        float4 v = ((const float4*)x)[i];
        __half h0x, l0x, h1x, l1x, h2x, l2x, h3x, l3x;
        split_h16(v.x, h0x, l0x); split_h16(v.y, h1x, l1x);
        split_h16(v.z, h2x, l2x); split_h16(v.w, h3x, l3x);
        *(uint2*)&g_xh[(size_t)i * 4] = make_uint2(h2_bits(h0x, h1x), h2_bits(h2x, h3x));
        *(uint2*)&g_xl[(size_t)i * 4] = make_uint2(h2_bits(l0x, l1x), h2_bits(l2x, l3x));
    }
    const int NW4 = G_ * I_ / 4;
    for (int d = 0; d < 2; d++) {
        const float* W = d ? Wb : Wf;
        for (int i = gtid; i < NW4; i += gsz) {
            float4 v = ((const float4*)W)[i];
            __half h0x, l0x, h1x, l1x, h2x, l2x, h3x, l3x;
            split_h16(v.x, h0x, l0x); split_h16(v.y, h1x, l1x);
            split_h16(v.z, h2x, l2x); split_h16(v.w, h3x, l3x);
            *(uint2*)&g_wh[d][(size_t)i * 4] = make_uint2(h2_bits(h0x, h1x), h2_bits(h2x, h3x));
            *(uint2*)&g_wl[d][(size_t)i * 4] = make_uint2(h2_bits(l0x, l1x), h2_bits(l2x, l3x));
        }
    }
    __half* hh = &g_hh[0][0][0][0];
    __half* hl = &g_hl[0][0][0][0];
    for (int i = gtid; i < 2 * B_ * H_; i += gsz) {
        __half hi, lo;
        split_h16(h0[i], hi, lo);
        hh[i] = hi; hl[i] = lo;
    }
}

// ---------------- xproj: 3xFP16 from pre-split inputs; cp.async fill ----------------
// Safety: issue -> commit -> wait<0> -> __syncthreads -> MMA (CTA-wide ordering).
__global__ void __launch_bounds__(256, 2) xproj_kernel()
{
    extern __shared__ __align__(16) char smraw[];
    __half* Ah = (__half*)smraw;          // [128][72]
    __half* Al = Ah + 128 * 72;
    __half* Bh = Al + 128 * 72;           // [64][72]
    __half* Bl = Bh + 64 * 72;

    const int tid = threadIdx.x;
    const int dir = blockIdx.z;
    const __half* wh = g_wh[dir];
    const __half* wl = g_wl[dir];
    const size_t m0 = (size_t)blockIdx.y * 128;
    const int    n0 = blockIdx.x * 64;
    const int wid = tid >> 5;
    const int row0 = (wid & 3) * 32;
    const int col0 = (wid >> 2) * 32;

    wmma::fragment<wmma::accumulator, 16, 16, 16, float> am[2][2], ac[2][2];
    #pragma unroll
    for (int i = 0; i < 2; i++)
        #pragma unroll
        for (int j = 0; j < 2; j++) { wmma::fill_fragment(am[i][j], 0.f); wmma::fill_fragment(ac[i][j], 0.f); }

    for (int k0 = 0; k0 < I_; k0 += 64) {
        __syncthreads();   // prior MMA reads done before overwrite
        #pragma unroll
        for (int q = 0; q < 4; q++) {
            int ci = tid + q * 256;            // 1024 chunks: 128 rows x 8
            int r = ci >> 3, c8 = (ci & 7) * 8;
            cp_async_cg16(&Ah[r * 72 + c8], &g_xh[(m0 + r) * I_ + k0 + c8]);
        }
        #pragma unroll
        for (int q = 0; q < 4; q++) {
            int ci = tid + q * 256;
            int r = ci >> 3, c8 = (ci & 7) * 8;
            cp_async_cg16(&Al[r * 72 + c8], &g_xl[(m0 + r) * I_ + k0 + c8]);
        }
        #pragma unroll
        for (int q = 0; q < 2; q++) {
            int ci = tid + q * 256;            // 512 chunks: 64 rows x 8
            int r = ci >> 3, c8 = (ci & 7) * 8;
            cp_async_cg16(&Bh[r * 72 + c8], &wh[(size_t)(n0 + r) * I_ + k0 + c8]);
        }
        #pragma unroll
        for (int q = 0; q < 2; q++) {
            int ci = tid + q * 256;
            int r = ci >> 3, c8 = (ci & 7) * 8;
            cp_async_cg16(&Bl[r * 72 + c8], &wl[(size_t)(n0 + r) * I_ + k0 + c8]);
        }
        cp_async_commit_wait();
        __syncthreads();
        #pragma unroll
        for (int kk = 0; kk < 64; kk += 16) {
            wmma::fragment<wmma::matrix_a, 16, 16, 16, __half, wmma::row_major> a_h[2], a_l[2];
            #pragma unroll
            for (int i = 0; i < 2; i++) {
                wmma::load_matrix_sync(a_h[i], Ah + (row0 + 16 * i) * 72 + kk, 72);
                wmma::load_matrix_sync(a_l[i], Al + (row0 + 16 * i) * 72 + kk, 72);
            }
            #pragma unroll
            for (int j = 0; j < 2; j++) {
                wmma::fragment<wmma::matrix_b, 16, 16, 16, __half, wmma::col_major> b_h, b_l;
                wmma::load_matrix_sync(b_h, Bh + (col0 + 16 * j) * 72 + kk, 72);
                wmma::load_matrix_sync(b_l, Bl + (col0 + 16 * j) * 72 + kk, 72);
                #pragma unroll
                for (int i = 0; i < 2; i++) {
                    wmma::mma_sync(am[i][j], a_h[i], b_h, am[i][j]);
                    wmma::mma_sync(ac[i][j], a_l[i], b_h, ac[i][j]);
                    wmma::mma_sync(ac[i][j], a_h[i], b_l, ac[i][j]);
                }
            }
        }
    }
    float* outp = g_xproj + (size_t)dir * T_ * B_ * G_;
    #pragma unroll
    for (int i = 0; i < 2; i++)
        #pragma unroll
        for (int j = 0; j < 2; j++) {
            #pragma unroll
            for (int e = 0; e < am[i][j].num_elements; e++)
                am[i][j].x[e] += ac[i][j].x[e] * LO_INV;
            wmma::store_matrix_sync(outp + (m0 + row0 + 16 * i) * G_ + n0 + col0 + 16 * j,
                                    am[i][j], G_, wmma::mem_row_major);
        }
}

// ---------------- scan: EXACT R11 structure (proven): tid0 spin + syncthreads; 1-group fill
#define NCPD 64
#define HS 8
#define HSTR 520   // 1040B == 16 mod 128: conflict-free LDSM + 16B cp.async
#define RSTR 40    // granule stride 20 -> conflict-free float2 reduce

__global__ void __launch_bounds__(256, 1) scan_kernel(
    const float* __restrict__ c0,
    const float* __restrict__ Whf, const float* __restrict__ Whb,
    const float* __restrict__ bf,  const float* __restrict__ bb,
    float* __restrict__ out)
{
    extern __shared__ __align__(16) char smraw[];
    __half* hSh = (__half*)smraw;            // [64][520]
    __half* hSl = hSh + 64 * HSTR;           // [64][520]
    float*  red = (float*)(hSl + 64 * HSTR); // [8][64][40] warp partials
    float*  cS  = red + 8 * 64 * RSTR;       // [64][8]
    float*  bias_s = cS + 64 * 8;            // [32]

    const int cta = blockIdx.x;
    const int dir = cta / NCPD;
    const int j   = cta % NCPD;
    const float* Wh   = dir ? Whb : Whf;
    const float* bias = dir ? bb : bf;
    const float* xp = g_xproj + (size_t)dir * T_ * B_ * G_;
    const int tid  = threadIdx.x;
    const int w    = tid >> 5;
    const int lane = tid & 31;
    const int cb  = tid >> 2;
    const int hc0 = (tid & 3) * 2;

    // ---- prologue: stage split W slice (aliases h staging), build register frags ----
    {
        __half* Wsh = hSh;                   // [32][520]
        __half* Wsl = Wsh + 32 * HSTR;
        for (int idx = tid; idx < 32 * 512; idx += 256) {
            int c = idx >> 9, k = idx & 511;
            int wrow = (c >> 3) * H_ + j * HS + (c & 7);
            __half hi, lo;
            split_h16(Wh[(size_t)wrow * H_ + k], hi, lo);
            Wsh[c * HSTR + k] = hi;
            Wsl[c * HSTR + k] = lo;
        }
        if (tid < 32)
            bias_s[tid] = bias[(tid >> 3) * H_ + j * HS + (tid & 7)];
        #pragma unroll
        for (int idx = tid; idx < 64 * HS; idx += 256)
            cS[idx] = c0[((size_t)dir * B_ + (idx >> 3)) * H_ + j * HS + (idx & 7)];
        __syncthreads();
    }

    wmma::fragment<wmma::matrix_b, 16, 16, 16, __half, wmma::col_major> bW_h[2][4], bW_l[2][4];
    {
        const __half* Wsh = hSh;
        const __half* Wsl = Wsh + 32 * HSTR;
        #pragma unroll
        for (int j2 = 0; j2 < 2; j2++)
            #pragma unroll
            for (int t4 = 0; t4 < 4; t4++) {
                wmma::load_matrix_sync(bW_h[j2][t4], Wsh + (j2 * 16) * HSTR + w * 64 + t4 * 16, HSTR);
                wmma::load_matrix_sync(bW_l[j2][t4], Wsl + (j2 * 16) * HSTR + w * 64 + t4 * 16, HSTR);
            }
    }
    __syncthreads();   // W staging done; h staging region free

    volatile unsigned* barp = &g_bar[dir][0];

    for (int s = 0; s < T_; ++s) {
        const int cbuf = s & 1;
        const int t = dir ? (T_ - 1 - s) : s;
        const __half* hsrc_h = &g_hh[cbuf][dir][0][0];
        const __half* hsrc_l = &g_hl[cbuf][dir][0][0];
        const float* xpt = xp + (size_t)t * B_ * G_;

        // xg prefetch — issued BEFORE the barrier wait
        float2 xg2[4];
        #pragma unroll
        for (int g = 0; g < 4; g++)
            xg2[g] = *(const float2*)&xpt[(size_t)cb * G_ + g * H_ + j * HS + hc0];

        // wait for all CTAs to have finished step s-1 (CTA-wide ordering point)
        if (s > 0 && tid == 0) {
            unsigned target = (unsigned)s * NCPD;
            while (*barp < target) { }
        }
        __syncthreads();

        // per-warp fill via cp.async.cg
        #pragma unroll
        for (int q = 0; q < 16; q++) {
            int slot = lane + q * 32;
            int r = slot >> 3, c8 = (slot & 7) * 8;
            const int go = r * H_ + w * 64 + c8;
            const int so = r * HSTR + w * 64 + c8;
            cp_async_cg16(&hSh[so], &hsrc_h[go]);
            cp_async_cg16(&hSl[so], &hsrc_l[go]);
        }
        cp_async_commit_wait();
        __syncwarp();

        // MMA on own K-slice (LDSM); store partials to red[w]
        #pragma unroll
        for (int i = 0; i < 4; i++) {
            wmma::fragment<wmma::accumulator, 16, 16, 16, float> am[2], ac[2];
            wmma::fill_fragment(am[0], 0.f); wmma::fill_fragment(am[1], 0.f);
            wmma::fill_fragment(ac[0], 0.f); wmma::fill_fragment(ac[1], 0.f);
            #pragma unroll
            for (int t4 = 0; t4 < 4; t4++) {
                wmma::fragment<wmma::matrix_a, 16, 16, 16, __half, wmma::row_major> a_h, a_l;
                const int off = (i * 16) * HSTR + w * 64 + t4 * 16;
                wmma::load_matrix_sync(a_h, hSh + off, HSTR);
                wmma::load_matrix_sync(a_l, hSl + off, HSTR);
                #pragma unroll
                for (int j2 = 0; j2 < 2; j2++) {
                    wmma::mma_sync(am[j2], a_h, bW_h[j2][t4], am[j2]);
                    wmma::mma_sync(ac[j2], a_l, bW_h[j2][t4], ac[j2]);
                    wmma::mma_sync(ac[j2], a_h, bW_l[j2][t4], ac[j2]);
                }
            }
            #pragma unroll
            for (int j2 = 0; j2 < 2; j2++) {
                #pragma unroll
                for (int e = 0; e < am[j2].num_elements; e++)
                    am[j2].x[e] += ac[j2].x[e] * LO_INV;
                wmma::store_matrix_sync(red + w * (64 * RSTR) + (i * 16) * RSTR + j2 * 16,
                                        am[j2], RSTR, wmma::mem_row_major);
            }
        }
        __syncthreads();   // all partials visible

        // vectorized reduce + LSTM cell; write split h via .cg
        __half* hdst_h = &g_hh[cbuf ^ 1][dir][0][0];
        __half* hdst_l = &g_hl[cbuf ^ 1][dir][0][0];
        {
            float2 sum[4];
            #pragma unroll
            for (int g = 0; g < 4; g++) { sum[g].x = 0.f; sum[g].y = 0.f; }
            #pragma unroll
            for (int ww = 0; ww < 8; ww++) {
                const float* rw = red + ww * (64 * RSTR) + cb * RSTR + hc0;
                #pragma unroll
                for (int g = 0; g < 4; g++) {
                    float2 v = *(const float2*)&rw[g * 8];
                    sum[g].x += v.x; sum[g].y += v.y;
                }
            }
            #pragma unroll
            for (int g = 0; g < 4; g++) {
                float2 bsv = *(const float2*)&bias_s[g * 8 + hc0];
                sum[g].x += xg2[g].x + bsv.x;
                sum[g].y += xg2[g].y + bsv.y;
            }
            float2 cold = *(const float2*)&cS[cb * HS + hc0];
            float ii0 = fsig(sum[0].x), ii1 = fsig(sum[0].y);
            float ff0 = fsig(sum[1].x), ff1 = fsig(sum[1].y);
            float gg0 = ftanh(sum[2].x), gg1 = ftanh(sum[2].y);
            float oo0 = fsig(sum[3].x), oo1 = fsig(sum[3].y);
            float cv0 = ff0 * cold.x + ii0 * gg0;
            float cv1 = ff1 * cold.y + ii1 * gg1;
            *(float2*)&cS[cb * HS + hc0] = make_float2(cv0, cv1);
            float hv0 = oo0 * ftanh(cv0);
            float hv1 = oo1 * ftanh(cv1);
            __half h0a, l0a, h1a, l1a;
            split_h16(hv0, h0a, l0a);
            split_h16(hv1, h1a, l1a);
            const int ho = cb * H_ + j * HS + hc0;
            stcg_u32(&hdst_h[ho], h2_bits(h0a, h1a));
            stcg_u32(&hdst_l[ho], h2_bits(l0a, l1a));
            *(float2*)&out[((size_t)t * B_ + cb) * (2 * H_) + dir * H_ + j * HS + hc0] =
                make_float2(hv0, hv1);
        }
        __syncthreads();   // all h stores issued before arrive

        if (tid == 0) {
            __threadfence();
            atomicAdd(&g_bar[dir][0], 1u);
        }
    }
}

// ---------------- launch ----------------
extern "C" void kernel_launch(void* const* d_in, const int* in_sizes, int n_in,
                              void* d_out, int out_size)
{
    const float* x    = (const float*)d_in[0];
    const float* h0   = (const float*)d_in[1];
    const float* c0   = (const float*)d_in[2];
    const float* Wihf = (const float*)d_in[3];
    const float* Whhf = (const float*)d_in[4];
    const float* bf   = (const float*)d_in[5];
    const float* Wihb = (const float*)d_in[6];
    const float* Whhb = (const float*)d_in[7];
    const float* bb   = (const float*)d_in[8];
    float* out = (float*)d_out;

    cudaFuncSetAttribute(scan_kernel, cudaFuncAttributeMaxDynamicSharedMemorySize, 217216);
    cudaFuncSetAttribute(xproj_kernel, cudaFuncAttributeMaxDynamicSharedMemorySize, 55296);

    prep_kernel<<<256, 256>>>(x, Wihf, Wihb, h0);

    dim3 gx(G_ / 64, (T_ * B_) / 128, 2);
    xproj_kernel<<<gx, 256, 55296>>>();

    scan_kernel<<<128, 256, 217216>>>(c0, Whhf, Whhb, bf, bb, out);
}